// round 4
// baseline (speedup 1.0000x reference)
#include <cuda_runtime.h>
#include <math.h>

#define SEQ 20
#define H   128
#define NC  100000

// ---------------- device scratch (no allocations allowed) ----------------
__device__ float g_Xf[SEQ][4*H];          // x @ Wih_f^T + bih_f + bhh_f
__device__ float g_Xb[SEQ][4*H];          // x[rev] @ Wih_b^T + biases
__device__ float g_comb[SEQ][2*H];        // [fwd_h, bwd_h]
__device__ float g_Xl[SEQ][8*H];          // comb @ Wih_l^T + biases
__device__ float g_hl[SEQ][2*H];          // layer-2 hidden states
__device__ float g_gates1[2][SEQ][4*H];   // per-step gate buffers (layer 1)
__device__ float g_gates2[SEQ][8*H];      // per-step gate buffers (layer 2)
__device__ int   g_bar1[2][SEQ];          // per-step arrival counters, layer 1
__device__ int   g_bar2[SEQ];             // per-step arrival counters, layer 2

// ---------------- helpers ----------------
__device__ __forceinline__ void fma2(unsigned long long& d,
                                     unsigned long long a, unsigned long long b) {
    // packed fp32x2 FMA (Blackwell FFMA2) — only reachable via PTX
    asm("fma.rn.f32x2 %0, %1, %2, %0;" : "+l"(d) : "l"(a), "l"(b));
}
__device__ __forceinline__ float sum2(unsigned long long v) {
    float lo, hi;
    asm("mov.b64 {%0, %1}, %2;" : "=f"(lo), "=f"(hi) : "l"(v));
    return lo + hi;
}
__device__ __forceinline__ float sigm(float x) { return 1.0f / (1.0f + expf(-x)); }

// =====================================================================
// proj_kernel<K>: out[t][n] = sum_k A[t][k]*W[n][k] + b1[n] (+ b2[n])
// for t in [0,20). One block handles a 64-wide n-tile; W tile staged in
// padded shared (stride = K+4 -> conflict-free LDS.128 across rows).
// a_sel: 0=A param, 1=g_comb, 2=g_hl.  out_sel: 0=g_Xf 1=g_Xb 2=g_Xl 3=param.
// rev: read A rows reversed (backward LSTM input).
// =====================================================================
template<int K>
__global__ void proj_kernel(const float* __restrict__ Apar,
                            const float* __restrict__ W,
                            const float* __restrict__ b1,
                            const float* __restrict__ b2,
                            float* __restrict__ Opar,
                            int N, int a_sel, int out_sel, int rev)
{
    extern __shared__ float sm[];
    const int stride = K + 4;
    float* sW = sm;                    // 64 * stride
    float* sA = sm + 64 * stride;      // SEQ * K (16B aligned: 64*stride*4 % 16 == 0)

    const int tid   = threadIdx.x;     // 128 threads
    const int nbase = blockIdx.x * 64;

    const float* A = (a_sel == 0) ? Apar
                   : (a_sel == 1) ? &g_comb[0][0] : &g_hl[0][0];
    float* out = (out_sel == 0) ? &g_Xf[0][0]
               : (out_sel == 1) ? &g_Xb[0][0]
               : (out_sel == 2) ? &g_Xl[0][0] : Opar;

    // stage A (optionally time-reversed)
    for (int idx = tid; idx < SEQ * K; idx += blockDim.x) {
        int t = idx / K, k = idx - t * K;
        sA[idx] = rev ? A[(SEQ - 1 - t) * K + k] : A[idx];
    }
    // stage 64 x K weight tile, coalesced float4, zero-fill OOB rows
    const int k4n = K >> 2;
    const float4* W4 = reinterpret_cast<const float4*>(W);
    for (int idx = tid; idx < 64 * k4n; idx += blockDim.x) {
        int r = idx / k4n, k4 = idx - r * k4n;
        int n = nbase + r;
        float4 v = (n < N) ? W4[(long)n * k4n + k4] : make_float4(0.f, 0.f, 0.f, 0.f);
        *reinterpret_cast<float4*>(&sW[r * stride + 4 * k4]) = v;
    }
    __syncthreads();

    const int nl = tid & 63;                 // local n
    const int th = (tid >> 6) * (SEQ / 2);   // t-half: rows 0..9 or 10..19

    unsigned long long acc[SEQ / 2];
    #pragma unroll
    for (int i = 0; i < SEQ / 2; i++) acc[i] = 0ull;

    const float* wrow = &sW[nl * stride];
    #pragma unroll 2
    for (int k4 = 0; k4 < k4n; k4++) {
        ulonglong2 w = *reinterpret_cast<const ulonglong2*>(&wrow[4 * k4]);
        #pragma unroll
        for (int tt = 0; tt < SEQ / 2; tt++) {
            ulonglong2 a = *reinterpret_cast<const ulonglong2*>(&sA[(th + tt) * K + 4 * k4]);
            fma2(acc[tt], w.x, a.x);
            fma2(acc[tt], w.y, a.y);
        }
    }
    const int n = nbase + nl;
    if (n < N) {
        float bias = b1[n] + (b2 ? b2[n] : 0.0f);
        #pragma unroll
        for (int tt = 0; tt < SEQ / 2; tt++)
            out[(long)(th + tt) * N + n] = sum2(acc[tt]) + bias;
    }
}

// =====================================================================
__global__ void zero_bar_kernel()
{
    int tid = threadIdx.x;
    if (tid < 2 * SEQ) ((int*)g_bar1)[tid] = 0;
    if (tid < SEQ)     g_bar2[tid] = 0;
}

// =====================================================================
// rec1: layer-1 LSTM recurrences. 8 blocks: dir = blk>>2, slice = blk&3.
// Each block owns 128 gate rows with its Whh slice resident in shared.
// Per step: gate slice -> global, spin barrier (4 blocks/dir), every block
// redundantly computes the h/c update. slice 0 writes g_comb.
// =====================================================================
__global__ void rec1_kernel(const float* __restrict__ Whh_f,
                            const float* __restrict__ Whh_b,
                            const float* __restrict__ h0f, const float* __restrict__ c0f,
                            const float* __restrict__ h0b, const float* __restrict__ c0b)
{
    extern __shared__ float sm[];
    const int stride = H + 4;          // 132 (== 4 mod 32 -> conflict-free)
    float* sW = sm;                    // 128 * 132
    __shared__ __align__(16) float sh[H];
    __shared__ __align__(16) float sc[H];

    const int tid = threadIdx.x;       // 128
    const int d = blockIdx.x >> 2;     // direction
    const int s = blockIdx.x & 3;      // row slice
    const int rowbase = s * 128;

    const float* Whh = d ? Whh_b : Whh_f;
    const float* h0  = d ? h0b : h0f;
    const float* c0  = d ? c0b : c0f;
    const float* X   = d ? &g_Xb[0][0] : &g_Xf[0][0];
    float* gates = &g_gates1[d][0][0];

    // stage Whh rows [rowbase, rowbase+128)
    const float4* W4 = reinterpret_cast<const float4*>(Whh);
    for (int idx = tid; idx < 128 * (H / 4); idx += blockDim.x) {
        int r = idx >> 5, k4 = idx & 31;
        *reinterpret_cast<float4*>(&sW[r * stride + 4 * k4]) = W4[(rowbase + r) * (H / 4) + k4];
    }
    sh[tid] = h0[tid];
    sc[tid] = c0[tid];
    __syncthreads();

    for (int t = 0; t < SEQ; t++) {
        // gate[row] = X[t][row] + Whh[row,:] . h
        unsigned long long a0 = 0ull, a1 = 0ull;
        const float* wrow = &sW[tid * stride];
        #pragma unroll
        for (int k4 = 0; k4 < H / 4; k4++) {
            ulonglong2 w = *reinterpret_cast<const ulonglong2*>(&wrow[4 * k4]);
            ulonglong2 h = *reinterpret_cast<const ulonglong2*>(&sh[4 * k4]);
            if (k4 & 1) { fma2(a1, w.x, h.x); fma2(a1, w.y, h.y); }
            else        { fma2(a0, w.x, h.x); fma2(a0, w.y, h.y); }
        }
        const int row = rowbase + tid;
        gates[t * 4 * H + row] = sum2(a0) + sum2(a1) + X[t * 4 * H + row];

        __threadfence();
        __syncthreads();
        if (tid == 0) {
            atomicAdd(&g_bar1[d][t], 1);
            while (*((volatile int*)&g_bar1[d][t]) < 4) { }
        }
        __syncthreads();
        __threadfence();

        // redundant full h/c update in every block (needs all 4 gates)
        {
            const float* gt = &gates[t * 4 * H];
            float gi = gt[tid], gf = gt[H + tid], gg = gt[2 * H + tid], go = gt[3 * H + tid];
            float c = sigm(gf) * sc[tid] + sigm(gi) * tanhf(gg);
            float h = sigm(go) * tanhf(c);
            sc[tid] = c;
            sh[tid] = h;
            if (s == 0) g_comb[t][d * H + tid] = h;   // scan order kept (bwd NOT flipped)
        }
        __syncthreads();
    }
}

// =====================================================================
// rec2: layer-2 LSTM (hidden 2H=256, 8H=1024 gate rows). 16 blocks x 64 rows,
// Whh_l slice (64 x 256 fp32 = 64KB) resident in shared.
// =====================================================================
__global__ void rec2_kernel(const float* __restrict__ Whh_l,
                            const float* __restrict__ h0l,
                            const float* __restrict__ c0l)
{
    extern __shared__ float sm[];
    const int K2 = 2 * H;              // 256
    const int stride = K2 + 4;         // 260
    float* sW = sm;                    // 64 * 260
    __shared__ __align__(16) float sh[2 * H];
    __shared__ __align__(16) float sc[2 * H];

    const int tid = threadIdx.x;       // 64
    const int rowbase = blockIdx.x * 64;

    const float4* W4 = reinterpret_cast<const float4*>(Whh_l);
    for (int idx = tid; idx < 64 * (K2 / 4); idx += blockDim.x) {
        int r = idx >> 6, k4 = idx & 63;
        *reinterpret_cast<float4*>(&sW[r * stride + 4 * k4]) = W4[(rowbase + r) * (K2 / 4) + k4];
    }
    #pragma unroll
    for (int i = 0; i < 4; i++) {
        sh[tid + i * 64] = h0l[tid + i * 64];
        sc[tid + i * 64] = c0l[tid + i * 64];
    }
    __syncthreads();

    for (int t = 0; t < SEQ; t++) {
        unsigned long long acc[4] = {0ull, 0ull, 0ull, 0ull};
        const float* wrow = &sW[tid * stride];
        #pragma unroll
        for (int k4 = 0; k4 < K2 / 4; k4++) {
            ulonglong2 w = *reinterpret_cast<const ulonglong2*>(&wrow[4 * k4]);
            ulonglong2 h = *reinterpret_cast<const ulonglong2*>(&sh[4 * k4]);
            fma2(acc[k4 & 3], w.x, h.x);
            fma2(acc[k4 & 3], w.y, h.y);
        }
        const int row = rowbase + tid;
        g_gates2[t][row] = sum2(acc[0]) + sum2(acc[1]) + sum2(acc[2]) + sum2(acc[3])
                         + g_Xl[t][row];

        __threadfence();
        __syncthreads();
        if (tid == 0) {
            atomicAdd(&g_bar2[t], 1);
            while (*((volatile int*)&g_bar2[t]) < 16) { }
        }
        __syncthreads();
        __threadfence();

        // redundant update of 256-dim h/c: 4 elements per thread
        const float* gt = &g_gates2[t][0];
        #pragma unroll
        for (int i = 0; i < 4; i++) {
            int k = tid + i * 64;
            float gi = gt[k], gf = gt[K2 + k], gg = gt[2 * K2 + k], go = gt[3 * K2 + k];
            float c = sigm(gf) * sc[k] + sigm(gi) * tanhf(gg);
            float h = sigm(go) * tanhf(c);
            sc[k] = c;
            sh[k] = h;
            if (blockIdx.x == 0) g_hl[t][k] = h;
        }
        __syncthreads();
    }
}

// =====================================================================
extern "C" void kernel_launch(void* const* d_in, const int* in_sizes, int n_in,
                              void* d_out, int out_size)
{
    const float* x     = (const float*)d_in[0];
    const float* h0f   = (const float*)d_in[1];
    const float* c0f   = (const float*)d_in[2];
    const float* h0b   = (const float*)d_in[3];
    const float* c0b   = (const float*)d_in[4];
    const float* h0l   = (const float*)d_in[5];
    const float* c0l   = (const float*)d_in[6];
    const float* Wih_f = (const float*)d_in[7];
    const float* Whh_f = (const float*)d_in[8];
    const float* bih_f = (const float*)d_in[9];
    const float* bhh_f = (const float*)d_in[10];
    const float* Wih_b = (const float*)d_in[11];
    const float* Whh_b = (const float*)d_in[12];
    const float* bih_b = (const float*)d_in[13];
    const float* bhh_b = (const float*)d_in[14];
    const float* Wih_l = (const float*)d_in[15];
    const float* Whh_l = (const float*)d_in[16];
    const float* bih_l = (const float*)d_in[17];
    const float* bhh_l = (const float*)d_in[18];
    const float* Wlin  = (const float*)d_in[19];
    const float* blin  = (const float*)d_in[20];
    float* out = (float*)d_out;

    const int smem_p128 = (64 * (128 + 4) + SEQ * 128) * 4;   // 44032
    const int smem_p256 = (64 * (256 + 4) + SEQ * 256) * 4;   // 87040
    const int smem_r1   = 128 * (128 + 4) * 4;                // 67584
    const int smem_r2   = 64 * (256 + 4) * 4;                 // 66560

    cudaFuncSetAttribute(proj_kernel<128>, cudaFuncAttributeMaxDynamicSharedMemorySize, smem_p128);
    cudaFuncSetAttribute(proj_kernel<256>, cudaFuncAttributeMaxDynamicSharedMemorySize, smem_p256);
    cudaFuncSetAttribute(rec1_kernel,      cudaFuncAttributeMaxDynamicSharedMemorySize, smem_r1);
    cudaFuncSetAttribute(rec2_kernel,      cudaFuncAttributeMaxDynamicSharedMemorySize, smem_r2);

    // 1) x-projections for both layer-1 directions (parallel GEMMs)
    proj_kernel<128><<<8, 128, smem_p128>>>(x, Wih_f, bih_f, bhh_f, nullptr,
                                            4 * H, /*a*/0, /*out*/0, /*rev*/0);
    proj_kernel<128><<<8, 128, smem_p128>>>(x, Wih_b, bih_b, bhh_b, nullptr,
                                            4 * H, 0, 1, 1);
    // 2) reset spin-barrier counters (graph-replay safe)
    zero_bar_kernel<<<1, 64>>>();
    // 3) layer-1 recurrences (fwd + bwd in lockstep, 4 blocks each)
    rec1_kernel<<<8, 128, smem_r1>>>(Whh_f, Whh_b, h0f, c0f, h0b, c0b);
    // 4) layer-2 x-projection: comb @ Wih_l^T + biases
    proj_kernel<256><<<16, 128, smem_p256>>>(nullptr, Wih_l, bih_l, bhh_l, nullptr,
                                             8 * H, 1, 2, 0);
    // 5) layer-2 recurrence
    rec2_kernel<<<16, 64, smem_r2>>>(Whh_l, h0l, c0l);
    // 6) final linear head: [20,100000] = hl @ Wlin^T + blin
    proj_kernel<256><<<(NC + 63) / 64, 128, smem_p256>>>(nullptr, Wlin, blin, nullptr,
                                                         out, NC, 2, 3, 0);
}

// round 5
// speedup vs baseline: 1.0001x; 1.0001x over previous
#include <cuda_runtime.h>
#include <math.h>

#define SEQ 20
#define H   128
#define NC  100000

// ---------------- device scratch (no allocations allowed) ----------------
__device__ float g_Xf[SEQ][4*H];          // x @ Wih_f^T + bih_f + bhh_f
__device__ float g_Xb[SEQ][4*H];          // x[rev] @ Wih_b^T + biases
__device__ float g_comb[SEQ][2*H];        // [fwd_h, bwd_h]
__device__ float g_Xl[SEQ][8*H];          // comb @ Wih_l^T + biases
__device__ float g_hl[SEQ][2*H];          // layer-2 hidden states
__device__ float g_gates1[2][SEQ][4*H];   // per-step gate buffers (layer 1)
__device__ float g_gates2[SEQ][8*H];      // per-step gate buffers (layer 2)
__device__ int   g_bar1[2][SEQ];          // per-step arrival counters, layer 1
__device__ int   g_bar2[SEQ];             // per-step arrival counters, layer 2

// ---------------- helpers ----------------
__device__ __forceinline__ void fma2(unsigned long long& d,
                                     unsigned long long a, unsigned long long b) {
    // packed fp32x2 FMA (Blackwell FFMA2) — only reachable via PTX
    asm("fma.rn.f32x2 %0, %1, %2, %0;" : "+l"(d) : "l"(a), "l"(b));
}
__device__ __forceinline__ float sum2(unsigned long long v) {
    float lo, hi;
    asm("mov.b64 {%0, %1}, %2;" : "=f"(lo), "=f"(hi) : "l"(v));
    return lo + hi;
}
__device__ __forceinline__ float sigm(float x) { return 1.0f / (1.0f + expf(-x)); }

// =====================================================================
// proj_kernel<K>: out[t][n] = sum_k A[t][k]*W[n][k] + b1[n] (+ b2[n])
// for t in [0,20). One block handles a 64-wide n-tile; W tile staged in
// padded shared (stride = K+4 -> conflict-free LDS.128 across rows).
// a_sel: 0=A param, 1=g_comb, 2=g_hl.  out_sel: 0=g_Xf 1=g_Xb 2=g_Xl 3=param.
// rev: read A rows reversed (backward LSTM input).
// =====================================================================
template<int K>
__global__ void proj_kernel(const float* __restrict__ Apar,
                            const float* __restrict__ W,
                            const float* __restrict__ b1,
                            const float* __restrict__ b2,
                            float* __restrict__ Opar,
                            int N, int a_sel, int out_sel, int rev)
{
    extern __shared__ float sm[];
    const int stride = K + 4;
    float* sW = sm;                    // 64 * stride
    float* sA = sm + 64 * stride;      // SEQ * K (16B aligned: 64*stride*4 % 16 == 0)

    const int tid   = threadIdx.x;     // 128 threads
    const int nbase = blockIdx.x * 64;

    const float* A = (a_sel == 0) ? Apar
                   : (a_sel == 1) ? &g_comb[0][0] : &g_hl[0][0];
    float* out = (out_sel == 0) ? &g_Xf[0][0]
               : (out_sel == 1) ? &g_Xb[0][0]
               : (out_sel == 2) ? &g_Xl[0][0] : Opar;

    // stage A (optionally time-reversed)
    for (int idx = tid; idx < SEQ * K; idx += blockDim.x) {
        int t = idx / K, k = idx - t * K;
        sA[idx] = rev ? A[(SEQ - 1 - t) * K + k] : A[idx];
    }
    // stage 64 x K weight tile, coalesced float4, zero-fill OOB rows
    const int k4n = K >> 2;
    const float4* W4 = reinterpret_cast<const float4*>(W);
    for (int idx = tid; idx < 64 * k4n; idx += blockDim.x) {
        int r = idx / k4n, k4 = idx - r * k4n;
        int n = nbase + r;
        float4 v = (n < N) ? W4[(long)n * k4n + k4] : make_float4(0.f, 0.f, 0.f, 0.f);
        *reinterpret_cast<float4*>(&sW[r * stride + 4 * k4]) = v;
    }
    __syncthreads();

    const int nl = tid & 63;                 // local n
    const int th = (tid >> 6) * (SEQ / 2);   // t-half: rows 0..9 or 10..19

    unsigned long long acc[SEQ / 2];
    #pragma unroll
    for (int i = 0; i < SEQ / 2; i++) acc[i] = 0ull;

    const float* wrow = &sW[nl * stride];
    #pragma unroll 2
    for (int k4 = 0; k4 < k4n; k4++) {
        ulonglong2 w = *reinterpret_cast<const ulonglong2*>(&wrow[4 * k4]);
        #pragma unroll
        for (int tt = 0; tt < SEQ / 2; tt++) {
            ulonglong2 a = *reinterpret_cast<const ulonglong2*>(&sA[(th + tt) * K + 4 * k4]);
            fma2(acc[tt], w.x, a.x);
            fma2(acc[tt], w.y, a.y);
        }
    }
    const int n = nbase + nl;
    if (n < N) {
        float bias = b1[n] + (b2 ? b2[n] : 0.0f);
        #pragma unroll
        for (int tt = 0; tt < SEQ / 2; tt++)
            out[(long)(th + tt) * N + n] = sum2(acc[tt]) + bias;
    }
}

// =====================================================================
__global__ void zero_bar_kernel()
{
    int tid = threadIdx.x;
    if (tid < 2 * SEQ) ((int*)g_bar1)[tid] = 0;
    if (tid < SEQ)     g_bar2[tid] = 0;
}

// =====================================================================
// rec1: layer-1 LSTM recurrences. 8 blocks: dir = blk>>2, slice = blk&3.
// Each block owns 128 gate rows with its Whh slice resident in shared.
// Per step: gate slice -> global, spin barrier (4 blocks/dir), every block
// redundantly computes the h/c update. slice 0 writes g_comb.
// =====================================================================
__global__ void rec1_kernel(const float* __restrict__ Whh_f,
                            const float* __restrict__ Whh_b,
                            const float* __restrict__ h0f, const float* __restrict__ c0f,
                            const float* __restrict__ h0b, const float* __restrict__ c0b)
{
    extern __shared__ float sm[];
    const int stride = H + 4;          // 132 (== 4 mod 32 -> conflict-free)
    float* sW = sm;                    // 128 * 132
    __shared__ __align__(16) float sh[H];
    __shared__ __align__(16) float sc[H];

    const int tid = threadIdx.x;       // 128
    const int d = blockIdx.x >> 2;     // direction
    const int s = blockIdx.x & 3;      // row slice
    const int rowbase = s * 128;

    const float* Whh = d ? Whh_b : Whh_f;
    const float* h0  = d ? h0b : h0f;
    const float* c0  = d ? c0b : c0f;
    const float* X   = d ? &g_Xb[0][0] : &g_Xf[0][0];
    float* gates = &g_gates1[d][0][0];

    // stage Whh rows [rowbase, rowbase+128)
    const float4* W4 = reinterpret_cast<const float4*>(Whh);
    for (int idx = tid; idx < 128 * (H / 4); idx += blockDim.x) {
        int r = idx >> 5, k4 = idx & 31;
        *reinterpret_cast<float4*>(&sW[r * stride + 4 * k4]) = W4[(rowbase + r) * (H / 4) + k4];
    }
    sh[tid] = h0[tid];
    sc[tid] = c0[tid];
    __syncthreads();

    for (int t = 0; t < SEQ; t++) {
        // gate[row] = X[t][row] + Whh[row,:] . h
        unsigned long long a0 = 0ull, a1 = 0ull;
        const float* wrow = &sW[tid * stride];
        #pragma unroll
        for (int k4 = 0; k4 < H / 4; k4++) {
            ulonglong2 w = *reinterpret_cast<const ulonglong2*>(&wrow[4 * k4]);
            ulonglong2 h = *reinterpret_cast<const ulonglong2*>(&sh[4 * k4]);
            if (k4 & 1) { fma2(a1, w.x, h.x); fma2(a1, w.y, h.y); }
            else        { fma2(a0, w.x, h.x); fma2(a0, w.y, h.y); }
        }
        const int row = rowbase + tid;
        gates[t * 4 * H + row] = sum2(a0) + sum2(a1) + X[t * 4 * H + row];

        __threadfence();
        __syncthreads();
        if (tid == 0) {
            atomicAdd(&g_bar1[d][t], 1);
            while (*((volatile int*)&g_bar1[d][t]) < 4) { }
        }
        __syncthreads();
        __threadfence();

        // redundant full h/c update in every block (needs all 4 gates)
        {
            const float* gt = &gates[t * 4 * H];
            float gi = gt[tid], gf = gt[H + tid], gg = gt[2 * H + tid], go = gt[3 * H + tid];
            float c = sigm(gf) * sc[tid] + sigm(gi) * tanhf(gg);
            float h = sigm(go) * tanhf(c);
            sc[tid] = c;
            sh[tid] = h;
            if (s == 0) g_comb[t][d * H + tid] = h;   // scan order kept (bwd NOT flipped)
        }
        __syncthreads();
    }
}

// =====================================================================
// rec2: layer-2 LSTM (hidden 2H=256, 8H=1024 gate rows). 16 blocks x 64 rows,
// Whh_l slice (64 x 256 fp32 = 64KB) resident in shared.
// =====================================================================
__global__ void rec2_kernel(const float* __restrict__ Whh_l,
                            const float* __restrict__ h0l,
                            const float* __restrict__ c0l)
{
    extern __shared__ float sm[];
    const int K2 = 2 * H;              // 256
    const int stride = K2 + 4;         // 260
    float* sW = sm;                    // 64 * 260
    __shared__ __align__(16) float sh[2 * H];
    __shared__ __align__(16) float sc[2 * H];

    const int tid = threadIdx.x;       // 64
    const int rowbase = blockIdx.x * 64;

    const float4* W4 = reinterpret_cast<const float4*>(Whh_l);
    for (int idx = tid; idx < 64 * (K2 / 4); idx += blockDim.x) {
        int r = idx >> 6, k4 = idx & 63;
        *reinterpret_cast<float4*>(&sW[r * stride + 4 * k4]) = W4[(rowbase + r) * (K2 / 4) + k4];
    }
    #pragma unroll
    for (int i = 0; i < 4; i++) {
        sh[tid + i * 64] = h0l[tid + i * 64];
        sc[tid + i * 64] = c0l[tid + i * 64];
    }
    __syncthreads();

    for (int t = 0; t < SEQ; t++) {
        unsigned long long acc[4] = {0ull, 0ull, 0ull, 0ull};
        const float* wrow = &sW[tid * stride];
        #pragma unroll
        for (int k4 = 0; k4 < K2 / 4; k4++) {
            ulonglong2 w = *reinterpret_cast<const ulonglong2*>(&wrow[4 * k4]);
            ulonglong2 h = *reinterpret_cast<const ulonglong2*>(&sh[4 * k4]);
            fma2(acc[k4 & 3], w.x, h.x);
            fma2(acc[k4 & 3], w.y, h.y);
        }
        const int row = rowbase + tid;
        g_gates2[t][row] = sum2(acc[0]) + sum2(acc[1]) + sum2(acc[2]) + sum2(acc[3])
                         + g_Xl[t][row];

        __threadfence();
        __syncthreads();
        if (tid == 0) {
            atomicAdd(&g_bar2[t], 1);
            while (*((volatile int*)&g_bar2[t]) < 16) { }
        }
        __syncthreads();
        __threadfence();

        // redundant update of 256-dim h/c: 4 elements per thread
        const float* gt = &g_gates2[t][0];
        #pragma unroll
        for (int i = 0; i < 4; i++) {
            int k = tid + i * 64;
            float gi = gt[k], gf = gt[K2 + k], gg = gt[2 * K2 + k], go = gt[3 * K2 + k];
            float c = sigm(gf) * sc[k] + sigm(gi) * tanhf(gg);
            float h = sigm(go) * tanhf(c);
            sc[k] = c;
            sh[k] = h;
            if (blockIdx.x == 0) g_hl[t][k] = h;
        }
        __syncthreads();
    }
}

// =====================================================================
extern "C" void kernel_launch(void* const* d_in, const int* in_sizes, int n_in,
                              void* d_out, int out_size)
{
    const float* x     = (const float*)d_in[0];
    const float* h0f   = (const float*)d_in[1];
    const float* c0f   = (const float*)d_in[2];
    const float* h0b   = (const float*)d_in[3];
    const float* c0b   = (const float*)d_in[4];
    const float* h0l   = (const float*)d_in[5];
    const float* c0l   = (const float*)d_in[6];
    const float* Wih_f = (const float*)d_in[7];
    const float* Whh_f = (const float*)d_in[8];
    const float* bih_f = (const float*)d_in[9];
    const float* bhh_f = (const float*)d_in[10];
    const float* Wih_b = (const float*)d_in[11];
    const float* Whh_b = (const float*)d_in[12];
    const float* bih_b = (const float*)d_in[13];
    const float* bhh_b = (const float*)d_in[14];
    const float* Wih_l = (const float*)d_in[15];
    const float* Whh_l = (const float*)d_in[16];
    const float* bih_l = (const float*)d_in[17];
    const float* bhh_l = (const float*)d_in[18];
    const float* Wlin  = (const float*)d_in[19];
    const float* blin  = (const float*)d_in[20];
    float* out = (float*)d_out;

    const int smem_p128 = (64 * (128 + 4) + SEQ * 128) * 4;   // 44032
    const int smem_p256 = (64 * (256 + 4) + SEQ * 256) * 4;   // 87040
    const int smem_r1   = 128 * (128 + 4) * 4;                // 67584
    const int smem_r2   = 64 * (256 + 4) * 4;                 // 66560

    cudaFuncSetAttribute(proj_kernel<128>, cudaFuncAttributeMaxDynamicSharedMemorySize, smem_p128);
    cudaFuncSetAttribute(proj_kernel<256>, cudaFuncAttributeMaxDynamicSharedMemorySize, smem_p256);
    cudaFuncSetAttribute(rec1_kernel,      cudaFuncAttributeMaxDynamicSharedMemorySize, smem_r1);
    cudaFuncSetAttribute(rec2_kernel,      cudaFuncAttributeMaxDynamicSharedMemorySize, smem_r2);

    // 1) x-projections for both layer-1 directions (parallel GEMMs)
    proj_kernel<128><<<8, 128, smem_p128>>>(x, Wih_f, bih_f, bhh_f, nullptr,
                                            4 * H, /*a*/0, /*out*/0, /*rev*/0);
    proj_kernel<128><<<8, 128, smem_p128>>>(x, Wih_b, bih_b, bhh_b, nullptr,
                                            4 * H, 0, 1, 1);
    // 2) reset spin-barrier counters (graph-replay safe)
    zero_bar_kernel<<<1, 64>>>();
    // 3) layer-1 recurrences (fwd + bwd in lockstep, 4 blocks each)
    rec1_kernel<<<8, 128, smem_r1>>>(Whh_f, Whh_b, h0f, c0f, h0b, c0b);
    // 4) layer-2 x-projection: comb @ Wih_l^T + biases
    proj_kernel<256><<<16, 128, smem_p256>>>(nullptr, Wih_l, bih_l, bhh_l, nullptr,
                                             8 * H, 1, 2, 0);
    // 5) layer-2 recurrence
    rec2_kernel<<<16, 64, smem_r2>>>(Whh_l, h0l, c0l);
    // 6) final linear head: [20,100000] = hl @ Wlin^T + blin
    proj_kernel<256><<<(NC + 63) / 64, 128, smem_p256>>>(nullptr, Wlin, blin, nullptr,
                                                         out, NC, 2, 3, 0);
}